// round 5
// baseline (speedup 1.0000x reference)
#include <cuda_runtime.h>

#define N_NODES 100000
#define N_EDGES 1600000
#define F 128
#define GRID2 296            // GEMM grid per chunk: 2 blocks/SM * 148
#define NCHUNK 4
#define CHUNK 25000
#define NBTOT (NCHUNK * GRID2)
#define BN_EPS 1e-5f

// -------- scratch (static device allocations are allowed) --------
__device__ int   g_row_ptr[N_NODES + 1];
__device__ float g_agg[(size_t)N_NODES * F];   // SpMM output (51.2 MB)
__device__ float g_psum[F * NBTOT];            // [feature][chunk*GRID2+block]
__device__ float g_psq [F * NBTOT];
__device__ float g_scale[F];
__device__ float g_shift[F];

// packed fp32x2 fma (Blackwell; ptxas won't auto-fuse this)
__device__ __forceinline__ unsigned long long ffma2(unsigned long long a,
                                                    unsigned long long b,
                                                    unsigned long long c) {
    unsigned long long d;
    asm("fma.rn.f32x2 %0, %1, %2, %3;" : "=l"(d) : "l"(a), "l"(b), "l"(c));
    return d;
}

// ---------------- kernel 0: row_ptr via boundary scatter ----------------
__global__ void k_rowptr(const int* __restrict__ adj_row) {
    int e = blockIdx.x * blockDim.x + threadIdx.x;
    if (e >= N_EDGES) return;
    int r1 = __ldg(&adj_row[e]);
    if (e == 0) {
        for (int r = 0; r <= r1; r++) g_row_ptr[r] = 0;
    }
    int r2 = (e + 1 < N_EDGES) ? __ldg(&adj_row[e + 1]) : N_NODES;
    for (int r = r1 + 1; r <= r2; r++) g_row_ptr[r] = e + 1;
}

// ---------------- kernel 1: SpMM, warp-per-node (chunked) ----------------
__global__ void __launch_bounds__(256)
k_spmm(const float* __restrict__ x,
       const int*   __restrict__ adj_col,
       const float* __restrict__ adj_val,
       int node_base, int node_cnt) {
    const int w = (blockIdx.x * blockDim.x + threadIdx.x) >> 5;
    if (w >= node_cnt) return;
    const int n = node_base + w;
    const int lane = threadIdx.x & 31;

    const int s = g_row_ptr[n];
    const int e = g_row_ptr[n + 1];
    const float4* xv = reinterpret_cast<const float4*>(x);

    float4 acc = make_float4(0.f, 0.f, 0.f, 0.f);

    int k = s;
    for (; k + 16 <= e; k += 16) {
        int col = 0; float val = 0.f;
        if (lane < 16) {
            col = __ldg(&adj_col[k + lane]);
            val = __ldg(&adj_val[k + lane]);
        }
#pragma unroll
        for (int j = 0; j < 16; j++) {
            int   c = __shfl_sync(0xffffffffu, col, j);
            float v = __shfl_sync(0xffffffffu, val, j);
            float4 xr = __ldg(&xv[(size_t)c * 32 + lane]);
            acc.x += v * xr.x; acc.y += v * xr.y;
            acc.z += v * xr.z; acc.w += v * xr.w;
        }
    }
    if (k < e) {
        int rem = e - k;                       // 1..15
        int col = 0; float val = 0.f;
        if (lane < rem) {
            col = __ldg(&adj_col[k + lane]);
            val = __ldg(&adj_val[k + lane]);
        }
#pragma unroll
        for (int j = 0; j < 15; j++) {
            if (j < rem) {
                int   c = __shfl_sync(0xffffffffu, col, j);
                float v = __shfl_sync(0xffffffffu, val, j);
                float4 xr = __ldg(&xv[(size_t)c * 32 + lane]);
                acc.x += v * xr.x; acc.y += v * xr.y;
                acc.z += v * xr.z; acc.w += v * xr.w;
            }
        }
    }

    reinterpret_cast<float4*>(g_agg)[(size_t)n * 32 + lane] = acc;
}

// ------------- kernel 2: Linear + BN partials (chunked) -------------
__global__ void __launch_bounds__(128, 2)
k_gemm(const float* __restrict__ fc_w,
       const float* __restrict__ fc_b,
       float*       __restrict__ h_out,
       int node_base, int node_cnt, int chunk) {
    __shared__ float agg_sm[8][F];

    const int t = threadIdx.x;

    unsigned long long w2[F / 2];
    const unsigned long long* wrow =
        reinterpret_cast<const unsigned long long*>(fc_w + (size_t)t * F);
#pragma unroll
    for (int i = 0; i < F / 2; i++) w2[i] = __ldg(&wrow[i]);
    const float bias = __ldg(&fc_b[t]);

    float bn_s = 0.f, bn_q = 0.f;
    const int node_end = node_base + node_cnt;

    for (int n0 = node_base + blockIdx.x * 8; n0 < node_end; n0 += gridDim.x * 8) {
        const int nv = min(8, node_end - n0);

        __syncthreads();
#pragma unroll
        for (int r = 0; r < 8; r++)
            if (r < nv) agg_sm[r][t] = g_agg[(size_t)(n0 + r) * F + t];
        __syncthreads();

        unsigned long long p0[8], p1[8];
#pragma unroll
        for (int r = 0; r < 8; r++) { p0[r] = 0ull; p1[r] = 0ull; }

#pragma unroll
        for (int j = 0; j < F / 4; j++) {
#pragma unroll
            for (int r = 0; r < 8; r++) {
                ulonglong2 aa =
                    reinterpret_cast<const ulonglong2*>(agg_sm[r])[j];
                p0[r] = ffma2(w2[2 * j],     aa.x, p0[r]);
                p1[r] = ffma2(w2[2 * j + 1], aa.y, p1[r]);
            }
        }
#pragma unroll
        for (int r = 0; r < 8; r++) {
            if (r < nv) {
                float2 f0 = *reinterpret_cast<float2*>(&p0[r]);
                float2 f1 = *reinterpret_cast<float2*>(&p1[r]);
                float hval = (f0.x + f0.y) + (f1.x + f1.y) + bias;
                h_out[(size_t)(n0 + r) * F + t] = hval;
                bn_s += hval;
                bn_q += hval * hval;
            }
        }
    }

    g_psum[t * NBTOT + chunk * GRID2 + blockIdx.x] = bn_s;
    g_psq [t * NBTOT + chunk * GRID2 + blockIdx.x] = bn_q;
}

// ---------------- kernel 3: finalize BN stats (parallel) ----------------
__global__ void k_stats(const float* __restrict__ bn_gamma,
                        const float* __restrict__ bn_beta) {
    __shared__ float ss[4], qq[4];
    const int o = blockIdx.x;
    const int t = threadIdx.x;

    float s = 0.f, q = 0.f;
    for (int b = t; b < NBTOT; b += 128) {
        s += g_psum[o * NBTOT + b];
        q += g_psq [o * NBTOT + b];
    }
#pragma unroll
    for (int off = 16; off; off >>= 1) {
        s += __shfl_down_sync(0xffffffffu, s, off);
        q += __shfl_down_sync(0xffffffffu, q, off);
    }
    if ((t & 31) == 0) { ss[t >> 5] = s; qq[t >> 5] = q; }
    __syncthreads();
    if (t == 0) {
        s = ss[0] + ss[1] + ss[2] + ss[3];
        q = qq[0] + qq[1] + qq[2] + qq[3];
        const float inv_n = 1.0f / (float)N_NODES;
        float mean = s * inv_n;
        float var  = q * inv_n - mean * mean;
        float isd  = rsqrtf(var + BN_EPS);
        float sc   = __ldg(&bn_gamma[o]) * isd;
        g_scale[o] = sc;
        g_shift[o] = __ldg(&bn_beta[o]) - mean * sc;
    }
}

// ---------------- kernel 4: in-place normalize ----------------
__global__ void k_norm(float* __restrict__ h) {
    const size_t total = (size_t)N_NODES * F;
    size_t i = ((size_t)blockIdx.x * blockDim.x + threadIdx.x) * 4;
    if (i >= total) return;
    int o = (int)(i & (F - 1));
    float4 v  = *reinterpret_cast<float4*>(h + i);
    float4 sc = *reinterpret_cast<const float4*>(g_scale + o);
    float4 sh = *reinterpret_cast<const float4*>(g_shift + o);
    v.x = v.x * sc.x + sh.x;
    v.y = v.y * sc.y + sh.y;
    v.z = v.z * sc.z + sh.z;
    v.w = v.w * sc.w + sh.w;
    *reinterpret_cast<float4*>(h + i) = v;
}

// ---------------- launch: fork/join pipeline ----------------
extern "C" void kernel_launch(void* const* d_in, const int* in_sizes, int n_in,
                              void* d_out, int out_size) {
    const float* x        = (const float*)d_in[0];
    const int*   adj_row  = (const int*)  d_in[1];
    const int*   adj_col  = (const int*)  d_in[2];
    const float* adj_val  = (const float*)d_in[3];
    const float* fc_w     = (const float*)d_in[4];
    const float* fc_b     = (const float*)d_in[5];
    const float* bn_gamma = (const float*)d_in[6];
    const float* bn_beta  = (const float*)d_in[7];
    float* out = (float*)d_out;

    // host-side handles only; created during capture host pass (runs once),
    // intentionally not destroyed (capture-safe; no device memory involved)
    cudaStream_t s1;
    cudaStreamCreateWithFlags(&s1, cudaStreamNonBlocking);
    cudaEvent_t ev_s[NCHUNK], ev_g;
    for (int c = 0; c < NCHUNK; c++)
        cudaEventCreateWithFlags(&ev_s[c], cudaEventDisableTiming);
    cudaEventCreateWithFlags(&ev_g, cudaEventDisableTiming);

    k_rowptr<<<(N_EDGES + 255) / 256, 256>>>(adj_row);

    for (int c = 0; c < NCHUNK; c++) {
        int base = c * CHUNK;
        int cnt  = (base + CHUNK <= N_NODES) ? CHUNK : (N_NODES - base);
        k_spmm<<<(cnt * 32 + 255) / 256, 256>>>(x, adj_col, adj_val, base, cnt);
        cudaEventRecord(ev_s[c], 0);
    }
    for (int c = 0; c < NCHUNK; c++) {
        int base = c * CHUNK;
        int cnt  = (base + CHUNK <= N_NODES) ? CHUNK : (N_NODES - base);
        cudaStreamWaitEvent(s1, ev_s[c], 0);
        k_gemm<<<GRID2, 128, 0, s1>>>(fc_w, fc_b, out, base, cnt, c);
    }
    cudaEventRecord(ev_g, s1);
    cudaStreamWaitEvent(0, ev_g, 0);

    k_stats<<<F, 128>>>(bn_gamma, bn_beta);
    k_norm<<<(N_NODES * F / 4 + 255) / 256, 256>>>(out);
}

// round 6
// speedup vs baseline: 1.2711x; 1.2711x over previous
#include <cuda_runtime.h>
#include <cuda_fp16.h>

#define N_NODES 100000
#define N_EDGES 1600000
#define F 128
#define GRID2 296            // GEMM grid: 2 blocks/SM * 148
#define BN_EPS 1e-5f

// -------- scratch (static device allocations are allowed) --------
__device__ int      g_row_ptr[N_NODES + 1];
__device__ __half   g_xh[(size_t)N_NODES * F]; // fp16 copy of x (25.6 MB)
__device__ float    g_agg[(size_t)N_NODES * F];// SpMM output (51.2 MB)
__device__ float    g_psum[F * GRID2];         // [feature][block]
__device__ float    g_psq [F * GRID2];
__device__ float    g_scale[F];
__device__ float    g_shift[F];

// packed fp32x2 fma (Blackwell; ptxas won't auto-fuse this)
__device__ __forceinline__ unsigned long long ffma2(unsigned long long a,
                                                    unsigned long long b,
                                                    unsigned long long c) {
    unsigned long long d;
    asm("fma.rn.f32x2 %0, %1, %2, %3;" : "=l"(d) : "l"(a), "l"(b), "l"(c));
    return d;
}

// ---------------- kernel 0a: row_ptr via boundary scatter ----------------
__global__ void k_rowptr(const int* __restrict__ adj_row) {
    int e = blockIdx.x * blockDim.x + threadIdx.x;
    if (e >= N_EDGES) return;
    int r1 = __ldg(&adj_row[e]);
    if (e == 0) {
        for (int r = 0; r <= r1; r++) g_row_ptr[r] = 0;
    }
    int r2 = (e + 1 < N_EDGES) ? __ldg(&adj_row[e + 1]) : N_NODES;
    for (int r = r1 + 1; r <= r2; r++) g_row_ptr[r] = e + 1;
}

// ---------------- kernel 0b: x -> fp16 copy ----------------
__global__ void k_xhalf(const float* __restrict__ x) {
    size_t i = ((size_t)blockIdx.x * blockDim.x + threadIdx.x) * 4;
    if (i >= (size_t)N_NODES * F) return;
    float4 v = *reinterpret_cast<const float4*>(x + i);
    __half2 h0 = __floats2half2_rn(v.x, v.y);
    __half2 h1 = __floats2half2_rn(v.z, v.w);
    uint2 out;
    out.x = *reinterpret_cast<unsigned*>(&h0);
    out.y = *reinterpret_cast<unsigned*>(&h1);
    *reinterpret_cast<uint2*>(reinterpret_cast<char*>(g_xh) + i * 2) = out;
}

// ---------------- kernel 1: SpMM, warp-per-node, fp16 gathers ----------------
// lane owns features [4*lane, 4*lane+4) as 8B uint2 of halfs.
__global__ void __launch_bounds__(256)
k_spmm(const int*   __restrict__ adj_col,
       const float* __restrict__ adj_val) {
    const int n = (blockIdx.x * blockDim.x + threadIdx.x) >> 5;
    if (n >= N_NODES) return;
    const int lane = threadIdx.x & 31;

    const int s = g_row_ptr[n];
    const int e = g_row_ptr[n + 1];
    const uint2* xv = reinterpret_cast<const uint2*>(g_xh);

    float4 acc = make_float4(0.f, 0.f, 0.f, 0.f);

    int k = s;
    for (; k + 16 <= e; k += 16) {
        int col = 0; float val = 0.f;
        if (lane < 16) {
            col = __ldg(&adj_col[k + lane]);
            val = __ldg(&adj_val[k + lane]);
        }
#pragma unroll
        for (int j = 0; j < 16; j++) {
            int   c = __shfl_sync(0xffffffffu, col, j);
            float v = __shfl_sync(0xffffffffu, val, j);
            uint2 raw = __ldg(&xv[(size_t)c * 32 + lane]);
            float2 f0 = __half22float2(*reinterpret_cast<__half2*>(&raw.x));
            float2 f1 = __half22float2(*reinterpret_cast<__half2*>(&raw.y));
            acc.x += v * f0.x; acc.y += v * f0.y;
            acc.z += v * f1.x; acc.w += v * f1.y;
        }
    }
    if (k < e) {
        int rem = e - k;                       // 1..15
        int col = 0; float val = 0.f;
        if (lane < rem) {
            col = __ldg(&adj_col[k + lane]);
            val = __ldg(&adj_val[k + lane]);
        }
#pragma unroll
        for (int j = 0; j < 15; j++) {
            if (j < rem) {
                int   c = __shfl_sync(0xffffffffu, col, j);
                float v = __shfl_sync(0xffffffffu, val, j);
                uint2 raw = __ldg(&xv[(size_t)c * 32 + lane]);
                float2 f0 = __half22float2(*reinterpret_cast<__half2*>(&raw.x));
                float2 f1 = __half22float2(*reinterpret_cast<__half2*>(&raw.y));
                acc.x += v * f0.x; acc.y += v * f0.y;
                acc.z += v * f1.x; acc.w += v * f1.y;
            }
        }
    }

    reinterpret_cast<float4*>(g_agg)[(size_t)n * 32 + lane] = acc;
}

// ------------- kernel 2: Linear (W row per thread) + BN partials -------------
__global__ void __launch_bounds__(128, 2)
k_gemm(const float* __restrict__ fc_w,
       const float* __restrict__ fc_b,
       float*       __restrict__ h_out) {
    __shared__ float agg_sm[8][F];

    const int t = threadIdx.x;

    unsigned long long w2[F / 2];
    const unsigned long long* wrow =
        reinterpret_cast<const unsigned long long*>(fc_w + (size_t)t * F);
#pragma unroll
    for (int i = 0; i < F / 2; i++) w2[i] = __ldg(&wrow[i]);
    const float bias = __ldg(&fc_b[t]);

    float bn_s = 0.f, bn_q = 0.f;

    for (int n0 = blockIdx.x * 8; n0 < N_NODES; n0 += gridDim.x * 8) {
        const int nv = min(8, N_NODES - n0);

        __syncthreads();
#pragma unroll
        for (int r = 0; r < 8; r++)
            if (r < nv) agg_sm[r][t] = g_agg[(size_t)(n0 + r) * F + t];
        __syncthreads();

        unsigned long long p0[8], p1[8];
#pragma unroll
        for (int r = 0; r < 8; r++) { p0[r] = 0ull; p1[r] = 0ull; }

#pragma unroll
        for (int j = 0; j < F / 4; j++) {
#pragma unroll
            for (int r = 0; r < 8; r++) {
                ulonglong2 aa =
                    reinterpret_cast<const ulonglong2*>(agg_sm[r])[j];
                p0[r] = ffma2(w2[2 * j],     aa.x, p0[r]);
                p1[r] = ffma2(w2[2 * j + 1], aa.y, p1[r]);
            }
        }
#pragma unroll
        for (int r = 0; r < 8; r++) {
            if (r < nv) {
                float2 f0 = *reinterpret_cast<float2*>(&p0[r]);
                float2 f1 = *reinterpret_cast<float2*>(&p1[r]);
                float hval = (f0.x + f0.y) + (f1.x + f1.y) + bias;
                h_out[(size_t)(n0 + r) * F + t] = hval;
                bn_s += hval;
                bn_q += hval * hval;
            }
        }
    }

    g_psum[t * GRID2 + blockIdx.x] = bn_s;     // transposed for coalesced stats
    g_psq [t * GRID2 + blockIdx.x] = bn_q;
}

// ---------------- kernel 3: finalize BN stats (parallel) ----------------
__global__ void k_stats(const float* __restrict__ bn_gamma,
                        const float* __restrict__ bn_beta) {
    __shared__ float ss[4], qq[4];
    const int o = blockIdx.x;
    const int t = threadIdx.x;

    float s = 0.f, q = 0.f;
    for (int b = t; b < GRID2; b += 128) {
        s += g_psum[o * GRID2 + b];
        q += g_psq [o * GRID2 + b];
    }
#pragma unroll
    for (int off = 16; off; off >>= 1) {
        s += __shfl_down_sync(0xffffffffu, s, off);
        q += __shfl_down_sync(0xffffffffu, q, off);
    }
    if ((t & 31) == 0) { ss[t >> 5] = s; qq[t >> 5] = q; }
    __syncthreads();
    if (t == 0) {
        s = ss[0] + ss[1] + ss[2] + ss[3];
        q = qq[0] + qq[1] + qq[2] + qq[3];
        const float inv_n = 1.0f / (float)N_NODES;
        float mean = s * inv_n;
        float var  = q * inv_n - mean * mean;
        float isd  = rsqrtf(var + BN_EPS);
        float sc   = __ldg(&bn_gamma[o]) * isd;
        g_scale[o] = sc;
        g_shift[o] = __ldg(&bn_beta[o]) - mean * sc;
    }
}

// ---------------- kernel 4: in-place normalize ----------------
__global__ void k_norm(float* __restrict__ h) {
    const size_t total = (size_t)N_NODES * F;
    size_t i = ((size_t)blockIdx.x * blockDim.x + threadIdx.x) * 4;
    if (i >= total) return;
    int o = (int)(i & (F - 1));
    float4 v  = *reinterpret_cast<float4*>(h + i);
    float4 sc = *reinterpret_cast<const float4*>(g_scale + o);
    float4 sh = *reinterpret_cast<const float4*>(g_shift + o);
    v.x = v.x * sc.x + sh.x;
    v.y = v.y * sc.y + sh.y;
    v.z = v.z * sc.z + sh.z;
    v.w = v.w * sc.w + sh.w;
    *reinterpret_cast<float4*>(h + i) = v;
}

// ---------------- launch (single stream) ----------------
extern "C" void kernel_launch(void* const* d_in, const int* in_sizes, int n_in,
                              void* d_out, int out_size) {
    const float* x        = (const float*)d_in[0];
    const int*   adj_row  = (const int*)  d_in[1];
    const int*   adj_col  = (const int*)  d_in[2];
    const float* adj_val  = (const float*)d_in[3];
    const float* fc_w     = (const float*)d_in[4];
    const float* fc_b     = (const float*)d_in[5];
    const float* bn_gamma = (const float*)d_in[6];
    const float* bn_beta  = (const float*)d_in[7];
    float* out = (float*)d_out;

    k_rowptr<<<(N_EDGES + 255) / 256, 256>>>(adj_row);
    k_xhalf<<<(N_NODES * F / 4 + 255) / 256, 256>>>(x);
    k_spmm<<<(N_NODES * 32 + 255) / 256, 256>>>(adj_col, adj_val);
    k_gemm<<<GRID2, 128>>>(fc_w, fc_b, out);
    k_stats<<<F, 128>>>(bn_gamma, bn_beta);
    k_norm<<<(N_NODES * F / 4 + 255) / 256, 256>>>(out);
}